// round 4
// baseline (speedup 1.0000x reference)
#include <cuda_runtime.h>
#include <stdint.h>

#define REP     640
#define ROWS    32
#define NPH     20            // supports out_dim <= 640
#define NKEY    (32 * NPH)
#define MAXM    32768
#define PADM    (MAXM + NKEY + 2)
#define STRIDE  33
#define SSTRIDE 641

// -------- device-global scratch --------
__device__ unsigned g_abp[MAXM];
__device__ float    g_cgv[MAXM];
__device__ int      g_key[MAXM];
__device__ int      g_pos[MAXM];
__device__ __align__(16) uint2 g_csr[PADM];   // bin-sorted, bins padded to even
__device__ int      g_rowptr[NKEY + 1];

// -------- fused preprocessing: detect + pack + prefix + pad + scatter (1 block) --
__global__ void k_prep(const void* __restrict__ r1, const void* __restrict__ r2,
                       const void* __restrict__ ro, const float* __restrict__ cg, int M) {
    __shared__ int scnt[NKEY];
    __shared__ int sstart[NKEY];
    __shared__ int ssum[1024];
    __shared__ unsigned sor;
    int t = threadIdx.x;

    for (int i = t; i < NKEY; i += 1024) scnt[i] = 0;
    if (t == 0) sor = 0u;
    __syncthreads();

    // int64 detection: odd 32-bit words of ro all zero -> int64
    {
        const unsigned* rr = (const unsigned*)ro;
        int lim = (M < 4096) ? M : 4096;        // safe word bound for int32 case
        unsigned v = 0;
        for (int i = 1 + 2 * t; i < lim; i += 2048) v |= rr[i];
        if (v) sor = 1u;                        // benign race, same value
    }
    __syncthreads();
    int is64 = (sor == 0u);

    // pack + histogram (shared atomics)
    for (int i = t; i < M; i += 1024) {
        int a, b, o;
        if (is64) {
            a = (int)((const long long*)r1)[i];
            b = (int)((const long long*)r2)[i];
            o = (int)((const long long*)ro)[i];
        } else {
            a = ((const int*)r1)[i];
            b = ((const int*)r2)[i];
            o = ((const int*)ro)[i];
        }
        int key = (o & 31) * NPH + (o >> 5);
        g_abp[i] = (unsigned)(a * STRIDE) | ((unsigned)(b * STRIDE) << 16);
        g_cgv[i] = cg[i];
        g_key[i] = key;
        g_pos[i] = atomicAdd(&scnt[key], 1);
    }
    __syncthreads();

    // inclusive prefix over even-padded counts (Hillis-Steele, 1024 lanes)
    int pc = (t < NKEY) ? ((scnt[t] + 1) & ~1) : 0;
    ssum[t] = pc;
    __syncthreads();
    for (int off = 1; off < 1024; off <<= 1) {
        int u = (t >= off) ? ssum[t - off] : 0;
        __syncthreads();
        ssum[t] += u;
        __syncthreads();
    }
    if (t < NKEY) {
        int end = ssum[t];
        int st  = end - pc;
        sstart[t] = st;
        g_rowptr[t + 1] = end;
        if ((scnt[t] & 1) && (st + scnt[t]) < PADM)
            g_csr[st + scnt[t]] = make_uint2(0u, 0u);   // dummy pad entry
    }
    if (t == 0) g_rowptr[0] = 0;
    __syncthreads();

    // O(M) scatter
    for (int i = t; i < M; i += 1024) {
        int p = sstart[g_key[i]] + g_pos[i];
        if (p < PADM)
            g_csr[p] = make_uint2(g_abp[i], __float_as_uint(g_cgv[i]));
    }
}

// -------- main: 32 rows/CTA, warp-per-(o mod 32), 2 entries/iter --------
__global__ __launch_bounds__(1024, 1)
void k_main(const float* __restrict__ x1, const float* __restrict__ x2,
            float* __restrict__ out, int N, int out_dim, int csr_in_smem) {
    extern __shared__ float sm[];
    float* x1t  = sm;                                  // [REP][STRIDE]
    float* x2t  = sm + REP * STRIDE;
    int*   srow = (int*)(sm + 2 * REP * STRIDE);       // NKEY+1, padded to 644
    uint4* csrs = (uint4*)(sm + 2 * REP * STRIDE + 644);

    int tid  = threadIdx.x;
    int lane = tid & 31;
    int w    = tid >> 5;
    int rowbase = blockIdx.x * ROWS;

    // coalesced scalar loads, conflict-free transpose writes (lanes: consecutive c)
    for (int idx = tid; idx < ROWS * REP; idx += 1024) {
        int r = idx / REP;
        int c = idx - r * REP;
        int gr = rowbase + r;
        float v1 = 0.f, v2 = 0.f;
        if (gr < N) {
            v1 = x1[(size_t)gr * REP + c];
            v2 = x2[(size_t)gr * REP + c];
        }
        x1t[c * STRIDE + r] = v1;     // bank = (c + r) mod 32 : distinct per lane
        x2t[c * STRIDE + r] = v2;
    }
    for (int i = tid; i <= NKEY; i += 1024) srow[i] = g_rowptr[i];
    __syncthreads();
    int mpairs = srow[NKEY] >> 1;
    if (mpairs > PADM / 2) mpairs = PADM / 2;
    if (csr_in_smem) {
        const uint4* src = (const uint4*)g_csr;
        for (int i = tid; i < mpairs; i += 1024) csrs[i] = src[i];
        __syncthreads();
    }
    const uint4* c4 = csr_in_smem ? (const uint4*)csrs : (const uint4*)g_csr;

    float acc[NPH];
    int e = srow[w * NPH] >> 1;
#pragma unroll
    for (int ph = 0; ph < NPH; ++ph) {
        int e1 = srow[w * NPH + ph + 1] >> 1;
        float a = 0.f, b = 0.f;
        for (; e < e1; ++e) {
            uint4 ent = c4[e];                          // 2 entries, warp-uniform
            int a1 = (int)(ent.x & 0xffffu) + lane;
            int a2 = (int)(ent.x >> 16) + lane;
            a = fmaf(__uint_as_float(ent.y) * x1t[a1], x2t[a2], a);
            int b1 = (int)(ent.z & 0xffffu) + lane;
            int b2 = (int)(ent.z >> 16) + lane;
            b = fmaf(__uint_as_float(ent.w) * x1t[b1], x2t[b2], b);
        }
        acc[ph] = a + b;
    }
    __syncthreads();

    // stage in (dead) x-tile region, stride 641 (== 1 mod 32) both sides clean
    float* stg = sm;
#pragma unroll
    for (int ph = 0; ph < NPH; ++ph) {
        int o = ph * 32 + w;
        if (o < out_dim) stg[lane * SSTRIDE + o] = acc[ph];
    }
    __syncthreads();

    for (int i = tid; i < ROWS * out_dim; i += 1024) {
        int r = i / out_dim;
        int c = i - r * out_dim;
        int gr = rowbase + r;
        if (gr < N) out[(size_t)gr * out_dim + c] = stg[r * SSTRIDE + c];
    }
}

// -------- launcher --------
extern "C" void kernel_launch(void* const* d_in, const int* in_sizes, int n_in,
                              void* d_out, int out_size) {
    const float* x1 = (const float*)d_in[0];
    const float* x2 = (const float*)d_in[1];
    const float* cg = (const float*)d_in[2];
    const void*  r1 = d_in[3];
    const void*  r2 = d_in[4];
    const void*  ro = d_in[5];

    int M = in_sizes[2];
    if (M > MAXM) M = MAXM;
    int N = in_sizes[0] / REP;
    int out_dim = out_size / N;

    k_prep<<<1, 1024>>>(r1, r2, ro, cg, M);

    int x_b    = 2 * REP * STRIDE * (int)sizeof(float);   // 168960
    int srow_b = 644 * (int)sizeof(int);
    int csr_b  = ((M + NKEY + 2) & ~1) * 8;               // padded bound
    int csr_in_smem = (x_b + srow_b + csr_b <= 227 * 1024) ? 1 : 0;
    int smem = x_b + srow_b + (csr_in_smem ? csr_b : 0);

    cudaFuncSetAttribute(k_main, cudaFuncAttributeMaxDynamicSharedMemorySize, smem);
    k_main<<<(N + ROWS - 1) / ROWS, 1024, smem>>>(x1, x2, (float*)d_out,
                                                  N, out_dim, csr_in_smem);
}

// round 6
// speedup vs baseline: 1.2163x; 1.2163x over previous
#include <cuda_runtime.h>
#include <stdint.h>

#define REP     640
#define ROWS    32
#define NPH     20            // supports out_dim <= 640
#define NKEY    (32 * NPH)
#define MAXM    32768
#define PADM    (MAXM + NKEY + 2)
#define STRIDE  33
#define SSTRIDE 641

// -------- device-global scratch --------
__device__ unsigned g_abp[MAXM];
__device__ float    g_cgv[MAXM];
__device__ int      g_key[MAXM];
__device__ int      g_pos[MAXM];
__device__ __align__(16) uint2 g_csr[PADM];   // bin-sorted, bins padded to even
__device__ int      g_rowptr[NKEY + 1];

// -------- fused preprocessing: detect + pack + prefix + pad + scatter (1 block) --
__global__ void k_prep(const void* __restrict__ r1, const void* __restrict__ r2,
                       const void* __restrict__ ro, const float* __restrict__ cg, int M) {
    __shared__ int scnt[NKEY];
    __shared__ int sstart[NKEY];
    __shared__ int ssum[1024];
    __shared__ unsigned sor;
    int t = threadIdx.x;

    for (int i = t; i < NKEY; i += 1024) scnt[i] = 0;
    if (t == 0) sor = 0u;
    __syncthreads();

    // int64 detection: odd 32-bit words of ro all zero -> int64
    {
        const unsigned* rr = (const unsigned*)ro;
        int lim = (M < 4096) ? M : 4096;        // safe word bound for int32 case
        unsigned v = 0;
        for (int i = 1 + 2 * t; i < lim; i += 2048) v |= rr[i];
        if (v) sor = 1u;                        // benign race, same value
    }
    __syncthreads();
    int is64 = (sor == 0u);

    // pack + histogram (shared atomics)
    for (int i = t; i < M; i += 1024) {
        int a, b, o;
        if (is64) {
            a = (int)((const long long*)r1)[i];
            b = (int)((const long long*)r2)[i];
            o = (int)((const long long*)ro)[i];
        } else {
            a = ((const int*)r1)[i];
            b = ((const int*)r2)[i];
            o = ((const int*)ro)[i];
        }
        int key = (o & 31) * NPH + (o >> 5);
        g_abp[i] = (unsigned)(a * STRIDE) | ((unsigned)(b * STRIDE) << 16);
        g_cgv[i] = cg[i];
        g_key[i] = key;
        g_pos[i] = atomicAdd(&scnt[key], 1);
    }
    __syncthreads();

    // inclusive prefix over even-padded counts (Hillis-Steele, 1024 lanes)
    int pc = (t < NKEY) ? ((scnt[t] + 1) & ~1) : 0;
    ssum[t] = pc;
    __syncthreads();
    for (int off = 1; off < 1024; off <<= 1) {
        int u = (t >= off) ? ssum[t - off] : 0;
        __syncthreads();
        ssum[t] += u;
        __syncthreads();
    }
    if (t < NKEY) {
        int end = ssum[t];
        int st  = end - pc;
        sstart[t] = st;
        g_rowptr[t + 1] = end;
        if ((scnt[t] & 1) && (st + scnt[t]) < PADM)
            g_csr[st + scnt[t]] = make_uint2(0u, 0u);   // dummy pad entry
    }
    if (t == 0) g_rowptr[0] = 0;
    __syncthreads();

    // O(M) scatter
    for (int i = t; i < M; i += 1024) {
        int p = sstart[g_key[i]] + g_pos[i];
        if (p < PADM)
            g_csr[p] = make_uint2(g_abp[i], __float_as_uint(g_cgv[i]));
    }
}

// -------- main: 32 rows/CTA, warp-per-(o mod 32), 2 entries/iter --------
__global__ __launch_bounds__(1024, 1)
void k_main(const float* __restrict__ x1, const float* __restrict__ x2,
            float* __restrict__ out, int N, int out_dim, int csr_in_smem) {
    extern __shared__ float sm[];
    float* x1t  = sm;                                  // [REP][STRIDE]
    float* x2t  = sm + REP * STRIDE;
    int*   srow = (int*)(sm + 2 * REP * STRIDE);       // NKEY+1, padded to 644
    uint4* csrs = (uint4*)(sm + 2 * REP * STRIDE + 644);

    int tid  = threadIdx.x;
    int lane = tid & 31;
    int w    = tid >> 5;
    int rowbase = blockIdx.x * ROWS;

    // ---- tile load: LDG.128 coalesced + conflict-free scalar STS ----
    // warp w = (stripe s = w>>2, quad q = w&3); lane L: r = 4s + (L>>3),
    // c4 = 32i + 8q + (L&7).  STS bank = 4(L&7) + (L>>3) + k : bijective per k.
    if (rowbase + ROWS <= N) {
        int s = w >> 2, q = w & 3;
        int r  = s * 4 + (lane >> 3);
        int cq = q * 8 + (lane & 7);
        const float4* p1 = (const float4*)(x1 + (size_t)(rowbase + r) * REP);
        const float4* p2 = (const float4*)(x2 + (size_t)(rowbase + r) * REP);
#pragma unroll
        for (int i = 0; i < 5; ++i) {
            int c4 = i * 32 + cq;
            float4 v1 = p1[c4];
            float4 v2 = p2[c4];
            int base = c4 * (4 * STRIDE) + r;
            x1t[base]              = v1.x;
            x1t[base + STRIDE]     = v1.y;
            x1t[base + 2 * STRIDE] = v1.z;
            x1t[base + 3 * STRIDE] = v1.w;
            x2t[base]              = v2.x;
            x2t[base + STRIDE]     = v2.y;
            x2t[base + 2 * STRIDE] = v2.z;
            x2t[base + 3 * STRIDE] = v2.w;
        }
    } else {
        for (int idx = tid; idx < ROWS * REP; idx += 1024) {
            int r = idx / REP;
            int c = idx - r * REP;
            int gr = rowbase + r;
            float v1 = 0.f, v2 = 0.f;
            if (gr < N) {
                v1 = x1[(size_t)gr * REP + c];
                v2 = x2[(size_t)gr * REP + c];
            }
            x1t[c * STRIDE + r] = v1;
            x2t[c * STRIDE + r] = v2;
        }
    }
    for (int i = tid; i <= NKEY; i += 1024) srow[i] = g_rowptr[i];
    __syncthreads();
    int mpairs = srow[NKEY] >> 1;
    if (mpairs > PADM / 2) mpairs = PADM / 2;
    if (csr_in_smem) {
        const uint4* src = (const uint4*)g_csr;
        for (int i = tid; i < mpairs; i += 1024) csrs[i] = src[i];
        __syncthreads();
    }
    const uint4* c4p = csr_in_smem ? (const uint4*)csrs : (const uint4*)g_csr;

    float acc[NPH];
    int e = srow[w * NPH] >> 1;
#pragma unroll
    for (int ph = 0; ph < NPH; ++ph) {
        int e1 = srow[w * NPH + ph + 1] >> 1;
        float a = 0.f, b = 0.f;
        for (; e < e1; ++e) {
            uint4 ent = c4p[e];                         // 2 entries, warp-uniform
            int a1 = (int)(ent.x & 0xffffu) + lane;
            int a2 = (int)(ent.x >> 16) + lane;
            a = fmaf(__uint_as_float(ent.y) * x1t[a1], x2t[a2], a);
            int b1 = (int)(ent.z & 0xffffu) + lane;
            int b2 = (int)(ent.z >> 16) + lane;
            b = fmaf(__uint_as_float(ent.w) * x1t[b1], x2t[b2], b);
        }
        acc[ph] = a + b;
    }
    __syncthreads();

    // stage in (dead) x-tile region, stride 641 (== 1 mod 32) both sides clean
    float* stg = sm;
#pragma unroll
    for (int ph = 0; ph < NPH; ++ph) {
        int o = ph * 32 + w;
        if (o < out_dim) stg[lane * SSTRIDE + o] = acc[ph];
    }
    __syncthreads();

    for (int i = tid; i < ROWS * out_dim; i += 1024) {
        int r = i / out_dim;
        int c = i - r * out_dim;
        int gr = rowbase + r;
        if (gr < N) out[(size_t)gr * out_dim + c] = stg[r * SSTRIDE + c];
    }
}

// -------- launcher --------
extern "C" void kernel_launch(void* const* d_in, const int* in_sizes, int n_in,
                              void* d_out, int out_size) {
    const float* x1 = (const float*)d_in[0];
    const float* x2 = (const float*)d_in[1];
    const float* cg = (const float*)d_in[2];
    const void*  r1 = d_in[3];
    const void*  r2 = d_in[4];
    const void*  ro = d_in[5];

    int M = in_sizes[2];
    if (M > MAXM) M = MAXM;
    int N = in_sizes[0] / REP;
    int out_dim = out_size / N;

    k_prep<<<1, 1024>>>(r1, r2, ro, cg, M);

    int x_b    = 2 * REP * STRIDE * (int)sizeof(float);   // 168960
    int srow_b = 644 * (int)sizeof(int);
    int csr_b  = ((M + NKEY + 2) & ~1) * 8;               // padded bound
    int csr_in_smem = (x_b + srow_b + csr_b <= 227 * 1024) ? 1 : 0;
    int smem = x_b + srow_b + (csr_in_smem ? csr_b : 0);

    cudaFuncSetAttribute(k_main, cudaFuncAttributeMaxDynamicSharedMemorySize, smem);
    k_main<<<(N + ROWS - 1) / ROWS, 1024, smem>>>(x1, x2, (float*)d_out,
                                                  N, out_dim, csr_in_smem);
}